// round 8
// baseline (speedup 1.0000x reference)
#include <cuda_runtime.h>
#include <math.h>
#include <float.h>

#define NB   8
#define CIN  888
#define HW   1024
#define EC   66
#define DC   64

// ---------------- scratch (device globals; no allocation allowed) ----------
__device__ float g_x64  [NB*DC*HW];
__device__ float g_xsh  [NB*EC*HW];
__device__ float g_xf2  [NB*EC*HW];
__device__ float g_out64[NB*DC*HW];
__device__ float g_tmp2 [NB*DC*HW];
__device__ float g_feat [NB*6*HW];

// ---------------- K1: 1x1 conv (GEMM 64x1024x888 per batch) +
//                  channel-shuffle scatter ---------------------------------
__global__ __launch_bounds__(256) void k_gemm(const float* __restrict__ x,
                                              const float* __restrict__ W,
                                              const float* __restrict__ bias)
{
    __shared__ float Xs[24*64];
    __shared__ float Ws[24*64];
    const int n  = blockIdx.y;
    const int p0 = blockIdx.x * 64;
    const int t  = threadIdx.x;
    const int tx = t & 15, ty = t >> 4;
    const float* xn = x + (size_t)n*CIN*HW + p0;

    float acc[4][4];
#pragma unroll
    for (int i=0;i<4;i++)
#pragma unroll
        for (int j=0;j<4;j++) acc[i][j]=0.f;

    float rx[6], rw[6];
#pragma unroll
    for (int i=0;i<6;i++){ int e=t+i*256; int kk=e>>6, px=e&63; rx[i]=xn[kk*HW+px]; }
#pragma unroll
    for (int i=0;i<6;i++){ int e=t+i*256; int oc=e/24, kk=e-oc*24; rw[i]=W[oc*CIN+kk]; }

    for (int ch=0; ch<37; ch++){
        __syncthreads();
#pragma unroll
        for (int i=0;i<6;i++){ int e=t+i*256; int kk=e>>6, px=e&63; Xs[kk*64+px]=rx[i]; }
#pragma unroll
        for (int i=0;i<6;i++){ int e=t+i*256; int oc=e/24, kk=e-oc*24; Ws[kk*64+oc]=rw[i]; }
        __syncthreads();
        if (ch < 36){
            const int k0 = (ch+1)*24;
#pragma unroll
            for (int i=0;i<6;i++){ int e=t+i*256; int kk=e>>6, px=e&63; rx[i]=xn[(k0+kk)*HW+px]; }
#pragma unroll
            for (int i=0;i<6;i++){ int e=t+i*256; int oc=e/24, kk=e-oc*24; rw[i]=W[oc*CIN+k0+kk]; }
        }
#pragma unroll
        for (int kk=0; kk<24; kk++){
            float4 xv = *(const float4*)&Xs[kk*64 + tx*4];
            float4 wv = *(const float4*)&Ws[kk*64 + ty*4];
            acc[0][0]+=wv.x*xv.x; acc[0][1]+=wv.x*xv.y; acc[0][2]+=wv.x*xv.z; acc[0][3]+=wv.x*xv.w;
            acc[1][0]+=wv.y*xv.x; acc[1][1]+=wv.y*xv.y; acc[1][2]+=wv.y*xv.z; acc[1][3]+=wv.y*xv.w;
            acc[2][0]+=wv.z*xv.x; acc[2][1]+=wv.z*xv.y; acc[2][2]+=wv.z*xv.z; acc[2][3]+=wv.z*xv.w;
            acc[3][0]+=wv.w*xv.x; acc[3][1]+=wv.w*xv.y; acc[3][2]+=wv.w*xv.z; acc[3][3]+=wv.w*xv.w;
        }
    }

#pragma unroll
    for (int i=0;i<4;i++){
        const int oc = ty*4+i;
        const float bb = bias[oc];
        const int sc = (oc%3)*22 + oc/3;   // channel shuffle target (g=3)
#pragma unroll
        for (int j=0;j<4;j++){
            const int p = p0 + tx*4 + j;
            const float v = acc[i][j] + bb;
            g_x64[((size_t)n*DC+oc)*HW + p] = v;
            g_xsh[((size_t)n*EC+sc)*HW + p] = v;
        }
    }
}

// ---------------- K1b: per-pixel mean/max over 888 input channels ----------
__global__ __launch_bounds__(1024) void k_meanmax(const float* __restrict__ x)
{
    const int n = blockIdx.x;
    const int p = threadIdx.x;
    const float* xp = x + (size_t)n*CIN*HW + p;
    float s = 0.f, m = -FLT_MAX;
    for (int c=0;c<CIN;c++){
        const float v = xp[(size_t)c*HW];
        s += v;
        m = fmaxf(m, v);
    }
    g_xsh[((size_t)n*EC+43)*HW + p] = s * (1.f/888.f);  // mean -> shuffled ch 43
    g_xsh[((size_t)n*EC+65)*HW + p] = m;                 // max  -> shuffled ch 65
}

// ---------------- K2: multi-scale depthwise (3/5/7) + depthwise-3 pos-enc
//                  residual, fused per channel -----------------------------
__global__ __launch_bounds__(256) void k_branch_pe(
    const float* __restrict__ W3,const float* __restrict__ b3,
    const float* __restrict__ W5,const float* __restrict__ b5,
    const float* __restrict__ W7,const float* __restrict__ b7,
    const float* __restrict__ Wpe,const float* __restrict__ bpe)
{
    __shared__ float s0[38*38];
    __shared__ float s1[32*33];
    __shared__ float wsm[64];
    const int ch = blockIdx.x, n = blockIdx.y;
    const int t = threadIdx.x;
    int r; const float* Wb; float bb;
    if (ch < 22)      { r=1; Wb=W3+ch*9;       bb=b3[ch];    }
    else if (ch < 44) { r=2; Wb=W5+(ch-22)*25; bb=b5[ch-22]; }
    else              { r=3; Wb=W7+(ch-44)*49; bb=b7[ch-44]; }
    const int kw = 2*r+1, nw = kw*kw;
    if (t < nw) wsm[t] = Wb[t];
    if (t >= 49 && t < 58) wsm[t] = Wpe[ch*9 + t-49];
    const float bpev = bpe[ch];
    const float* in = g_xsh + ((size_t)n*EC+ch)*HW;
    for (int e=t; e<38*38; e+=256){
        const int sy = e/38 - 3, sx = e%38 - 3;
        s0[e] = (sy>=0 && sy<32 && sx>=0 && sx<32) ? in[sy*32+sx] : 0.f;
    }
    __syncthreads();
#pragma unroll
    for (int q=0;q<4;q++){
        const int p = t + q*256; const int y=p>>5, xx=p&31;
        float a = bb;
        for (int dy=-r; dy<=r; dy++)
            for (int dx=-r; dx<=r; dx++)
                a += wsm[(dy+r)*kw + dx+r] * s0[(y+3+dy)*38 + xx+3+dx];
        s1[y*33+xx] = a;
    }
    __syncthreads();
    float* out = g_xf2 + ((size_t)n*EC+ch)*HW;
#pragma unroll
    for (int q=0;q<4;q++){
        const int p = t + q*256; const int y=p>>5, xx=p&31;
        float a = bpev;
#pragma unroll
        for (int dy=-1; dy<=1; dy++){
            const int yy=y+dy;
#pragma unroll
            for (int dx=-1; dx<=1; dx++){
                const int xc=xx+dx;
                const float v = (yy>=0&&yy<32&&xc>=0&&xc<32) ? s1[yy*33+xc] : 0.f;
                a += wsm[49+(dy+1)*3+dx+1] * v;
            }
        }
        out[p] = s1[y*33+xx] + a;    // x_fused + pe-conv(x_fused)
    }
}

// ---------------- K3: LayerNorm(channels) + 3x3 conv 66->64 + GELU +
//                  residual(x64), fused per 8x8 tile -----------------------
__global__ __launch_bounds__(256) void k_mainconv(
    const float* __restrict__ lng, const float* __restrict__ lnb,
    const float* __restrict__ Wlast, const float* __restrict__ blast)
{
    __shared__ float sIn[EC*100];
    __shared__ float sg[EC], sb[EC];
    const int n = blockIdx.y;
    const int tile = blockIdx.x;
    const int ty0 = (tile>>2)*8, tx0 = (tile&3)*8;
    const int t = threadIdx.x;
    if (t < EC){ sg[t]=lng[t]; sb[t]=lnb[t]; }
    for (int e=t; e<EC*100; e+=256){
        const int c = e/100, rem = e-c*100, rr = rem/10, cc = rem-rr*10;
        const int gy = ty0-1+rr, gx = tx0-1+cc;
        sIn[e] = (gy>=0&&gy<32&&gx>=0&&gx<32) ?
                 g_xf2[((size_t)n*EC+c)*HW + gy*32+gx] : 0.f;
    }
    __syncthreads();
    if (t < 100){
        const int rr=t/10, cc=t-rr*10;
        const int gy=ty0-1+rr, gx=tx0-1+cc;
        if (gy>=0&&gy<32&&gx>=0&&gx<32){
            float s=0.f, sq=0.f;
#pragma unroll
            for (int c=0;c<EC;c++){ const float v=sIn[c*100+t]; s+=v; sq+=v*v; }
            const float mu = s*(1.f/66.f);
            const float var = sq*(1.f/66.f) - mu*mu;
            const float rs = rsqrtf(var + 1e-5f);
#pragma unroll
            for (int c=0;c<EC;c++)
                sIn[c*100+t] = (sIn[c*100+t]-mu)*rs*sg[c]+sb[c];
        }
    }
    __syncthreads();
    const int oc = t>>2, q = t&3;
    const int qy = (q>>1)*4, qx = (q&1)*4;
    const float bb = blast[oc];
    float acc[4][4];
#pragma unroll
    for (int i=0;i<4;i++)
#pragma unroll
        for (int j=0;j<4;j++) acc[i][j]=bb;
    const float* wl = Wlast + oc*EC*9;
    for (int c=0;c<EC;c++){
        float rIn[6][6];
        const int base = c*100 + qy*10 + qx;
#pragma unroll
        for (int i=0;i<6;i++)
#pragma unroll
            for (int j=0;j<6;j++) rIn[i][j] = sIn[base + i*10 + j];
        float w[9];
#pragma unroll
        for (int k=0;k<9;k++) w[k] = __ldg(wl + c*9 + k);
#pragma unroll
        for (int i=0;i<4;i++)
#pragma unroll
            for (int j=0;j<4;j++)
#pragma unroll
                for (int dy=0;dy<3;dy++)
#pragma unroll
                    for (int dx=0;dx<3;dx++)
                        acc[i][j] += w[dy*3+dx]*rIn[i+dy][j+dx];
    }
    const float* xr  = g_x64  + ((size_t)n*DC+oc)*HW;
    float*       out = g_out64 + ((size_t)n*DC+oc)*HW;
#pragma unroll
    for (int i=0;i<4;i++)
#pragma unroll
        for (int j=0;j<4;j++){
            const int p = (ty0+qy+i)*32 + tx0+qx+j;
            const float v = acc[i][j];
            const float ge = 0.5f*v*(1.f+erff(v*0.70710678118654752f));
            out[p] = ge + xr[p];
        }
}

// ---------------- K4: aux head dw3 -> dw5(dilation 3), fused per channel ---
__global__ __launch_bounds__(256) void k_aux(const float* __restrict__ Wa0,
                                             const float* __restrict__ Was)
{
    __shared__ float s0[34*34];
    __shared__ float s1[32*33];
    __shared__ float wsm[40];
    const int ch = blockIdx.x, n = blockIdx.y;
    const int t = threadIdx.x;
    if (t < 9)              wsm[t] = Wa0[ch*9+t];
    if (t >= 9 && t < 34)   wsm[t] = Was[ch*25 + t-9];
    const float* in = g_out64 + ((size_t)n*DC+ch)*HW;
    for (int e=t; e<34*34; e+=256){
        const int sy=e/34-1, sx=e%34-1;
        s0[e] = (sy>=0&&sy<32&&sx>=0&&sx<32)? in[sy*32+sx] : 0.f;
    }
    __syncthreads();
#pragma unroll
    for (int q=0;q<4;q++){
        const int p=t+q*256, y=p>>5, xx=p&31;
        float a=0.f;
#pragma unroll
        for (int dy=0;dy<3;dy++)
#pragma unroll
            for (int dx=0;dx<3;dx++)
                a += wsm[dy*3+dx]*s0[(y+dy)*34 + xx+dx];
        s1[y*33+xx]=a;
    }
    __syncthreads();
    float* out = g_tmp2 + ((size_t)n*DC+ch)*HW;
#pragma unroll
    for (int q=0;q<4;q++){
        const int p=t+q*256, y=p>>5, xx=p&31;
        float a=0.f;
#pragma unroll
        for (int ky=0;ky<5;ky++){
            const int yy = y + (ky-2)*3;
            if (yy<0||yy>=32) continue;
#pragma unroll
            for (int kx=0;kx<5;kx++){
                const int xc = xx + (kx-2)*3;
                if (xc<0||xc>=32) continue;
                a += wsm[9+ky*5+kx]*s1[yy*33+xc];
            }
        }
        out[p]=a;
    }
}

// ---------------- K5: 1x1 conv 64->6  (FIXED: full 384-weight load) --------
__global__ __launch_bounds__(256) void k_pw(const float* __restrict__ Wout)
{
    __shared__ float w[6*64];
    const int t = threadIdx.x;
    for (int i=t; i<384; i+=256) w[i] = Wout[i];   // <-- was `if (t<384)` under 256 threads
    __syncthreads();
    const int gp = blockIdx.x*256+t;
    const int n = gp>>10, p = gp&1023;
    const float* tp = g_tmp2 + (size_t)n*DC*HW + p;
    float acc[6]={0.f,0.f,0.f,0.f,0.f,0.f};
    for (int oc=0;oc<64;oc++){
        const float v = tp[(size_t)oc*HW];
#pragma unroll
        for (int k=0;k<6;k++) acc[k] += w[k*64+oc]*v;
    }
    float* f = g_feat + (size_t)n*6*HW + p;
#pragma unroll
    for (int k=0;k<6;k++) f[(size_t)k*HW] = acc[k];
}

// ---------------- K6: bilinear 32x32 -> 1024x1024 (half-pixel, clamped) ----
__global__ __launch_bounds__(256) void k_upsample(float* __restrict__ out)
{
    const int idx = blockIdx.x*256 + threadIdx.x;       // float4 units
    const int ox4 = idx & 255;
    const int oy  = (idx >> 8) & 1023;
    const int nk  = idx >> 18;
    if (nk >= NB*6) return;
    const float* f = g_feat + (size_t)nk*HW;

    const float sy = (oy + 0.5f)*0.03125f - 0.5f;
    const float fy = floorf(sy);
    const float wy = sy - fy;
    const int   iy = (int)fy;
    const int   y0 = min(max(iy,0),31);
    const int   y1 = min(iy+1,31);

    const int   ox0 = ox4*4;
    const float sx  = (ox0 + 0.5f)*0.03125f - 0.5f;
    const float fx  = floorf(sx);
    const float wx0 = sx - fx;
    const int   ix  = (int)fx;
    const int   x0  = min(max(ix,0),31);
    const int   x1  = min(ix+1,31);

    const float v00 = f[y0*32+x0], v01 = f[y0*32+x1];
    const float v10 = f[y1*32+x0], v11 = f[y1*32+x1];
    const float a = v00 + (v10-v00)*wy;
    const float b = v01 + (v11-v01)*wy;
    const float d = b - a;
    float4 o;
    o.x = a + d*wx0;
    o.y = a + d*(wx0+0.03125f);
    o.z = a + d*(wx0+0.0625f);
    o.w = a + d*(wx0+0.09375f);
    reinterpret_cast<float4*>(out)[idx] = o;
}

// ---------------- launch ----------------------------------------------------
extern "C" void kernel_launch(void* const* d_in, const int* in_sizes, int n_in,
                              void* d_out, int out_size)
{
    (void)out_size;
    // Identify tensors by element count; duplicates by order of appearance.
    const float *x=0,*W1=0,*b1=0,*W3=0,*b3=0,*W5=0,*b5=0,*W7=0,*b7=0;
    const float *Wpe=0,*bpe=0,*lng=0,*lnb=0,*Wlast=0,*blast=0,*Wa0=0,*Was=0,*Wout=0;
    int c22=0, c64=0, c66=0;
    for (int i=0;i<n_in;i++){
        const int s = in_sizes[i];
        const float* p = (const float*)d_in[i];
        switch (s){
            case 7274496: x=p; break;
            case 56832:   W1=p; break;
            case 198:     W3=p; break;
            case 550:     W5=p; break;
            case 1078:    W7=p; break;
            case 594:     Wpe=p; break;
            case 38016:   Wlast=p; break;
            case 576:     Wa0=p; break;
            case 1600:    Was=p; break;
            case 384:     Wout=p; break;
            case 64:      if (c64==0) b1=p; else blast=p; c64++; break;
            case 22:      if (c22==0) b3=p; else if (c22==1) b5=p; else b7=p; c22++; break;
            case 66:      if (c66==0) bpe=p; else if (c66==1) lng=p; else lnb=p; c66++; break;
            default: break; // h, w scalars
        }
    }

    k_gemm     <<<dim3(16,NB), 256>>>(x, W1, b1);
    k_meanmax  <<<NB, 1024>>>(x);
    k_branch_pe<<<dim3(EC,NB), 256>>>(W3,b3,W5,b5,W7,b7,Wpe,bpe);
    k_mainconv <<<dim3(16,NB), 256>>>(lng,lnb,Wlast,blast);
    k_aux      <<<dim3(DC,NB), 256>>>(Wa0,Was);
    k_pw       <<<32, 256>>>(Wout);
    k_upsample <<<(NB*6*1024*256)/256, 256>>>((float*)d_out);
}

// round 10
// speedup vs baseline: 1.1326x; 1.1326x over previous
#include <cuda_runtime.h>
#include <math.h>
#include <float.h>

#define NB   8
#define CIN  888
#define HW   1024
#define EC   66
#define DC   64

// ---------------- scratch (device globals; no allocation allowed) ----------
__device__ float g_x64  [NB*DC*HW];
__device__ float g_xsh  [NB*EC*HW];
__device__ float g_xf2  [NB*EC*HW];
__device__ float g_out64[NB*DC*HW];
__device__ float g_tmp2 [NB*DC*HW];
__device__ float g_feat [NB*6*HW];

// ---------------- K1: 1x1 conv (GEMM 64x1024x888 per batch) + mean/max +
//                  channel-shuffle scatter ---------------------------------
__global__ __launch_bounds__(256) void k_gemm(const float* __restrict__ x,
                                              const float* __restrict__ W,
                                              const float* __restrict__ bias)
{
    __shared__ float Xs[24*64];
    __shared__ float Ws[24*64];
    const int n  = blockIdx.y;
    const int p0 = blockIdx.x * 64;
    const int t  = threadIdx.x;
    const int tx = t & 15, ty = t >> 4;
    const float* xn = x + (size_t)n*CIN*HW + p0;

    float acc[4][4];
#pragma unroll
    for (int i=0;i<4;i++)
#pragma unroll
        for (int j=0;j<4;j++) acc[i][j]=0.f;
    float4 psum = make_float4(0.f,0.f,0.f,0.f);
    float4 pmax = make_float4(-FLT_MAX,-FLT_MAX,-FLT_MAX,-FLT_MAX);

    float rx[6], rw[6];
#pragma unroll
    for (int i=0;i<6;i++){ int e=t+i*256; int kk=e>>6, px=e&63; rx[i]=xn[kk*HW+px]; }
#pragma unroll
    for (int i=0;i<6;i++){ int e=t+i*256; int oc=e/24, kk=e-oc*24; rw[i]=W[oc*CIN+kk]; }

    for (int ch=0; ch<37; ch++){
        __syncthreads();
#pragma unroll
        for (int i=0;i<6;i++){ int e=t+i*256; int kk=e>>6, px=e&63; Xs[kk*64+px]=rx[i]; }
#pragma unroll
        for (int i=0;i<6;i++){ int e=t+i*256; int oc=e/24, kk=e-oc*24; Ws[kk*64+oc]=rw[i]; }
        __syncthreads();
        if (ch < 36){
            const int k0 = (ch+1)*24;
#pragma unroll
            for (int i=0;i<6;i++){ int e=t+i*256; int kk=e>>6, px=e&63; rx[i]=xn[(k0+kk)*HW+px]; }
#pragma unroll
            for (int i=0;i<6;i++){ int e=t+i*256; int oc=e/24, kk=e-oc*24; rw[i]=W[oc*CIN+k0+kk]; }
        }
#pragma unroll
        for (int kk=0; kk<24; kk++){
            float4 xv = *(const float4*)&Xs[kk*64 + tx*4];
            float4 wv = *(const float4*)&Ws[kk*64 + ty*4];
            acc[0][0]+=wv.x*xv.x; acc[0][1]+=wv.x*xv.y; acc[0][2]+=wv.x*xv.z; acc[0][3]+=wv.x*xv.w;
            acc[1][0]+=wv.y*xv.x; acc[1][1]+=wv.y*xv.y; acc[1][2]+=wv.y*xv.z; acc[1][3]+=wv.y*xv.w;
            acc[2][0]+=wv.z*xv.x; acc[2][1]+=wv.z*xv.y; acc[2][2]+=wv.z*xv.z; acc[2][3]+=wv.z*xv.w;
            acc[3][0]+=wv.w*xv.x; acc[3][1]+=wv.w*xv.y; acc[3][2]+=wv.w*xv.z; acc[3][3]+=wv.w*xv.w;
            if (ty==0){
                psum.x+=xv.x; psum.y+=xv.y; psum.z+=xv.z; psum.w+=xv.w;
                pmax.x=fmaxf(pmax.x,xv.x); pmax.y=fmaxf(pmax.y,xv.y);
                pmax.z=fmaxf(pmax.z,xv.z); pmax.w=fmaxf(pmax.w,xv.w);
            }
        }
    }

#pragma unroll
    for (int i=0;i<4;i++){
        const int oc = ty*4+i;
        const float bb = bias[oc];
        const int sc = (oc%3)*22 + oc/3;   // channel shuffle target (g=3)
#pragma unroll
        for (int j=0;j<4;j++){
            const int p = p0 + tx*4 + j;
            const float v = acc[i][j] + bb;
            g_x64[((size_t)n*DC+oc)*HW + p] = v;
            g_xsh[((size_t)n*EC+sc)*HW + p] = v;
        }
    }
    if (ty==0){
        const int p = p0 + tx*4;
        const float inv = 1.f/888.f;
        float* m1 = &g_xsh[((size_t)n*EC+43)*HW + p];  // mean -> shuffled ch 43
        float* m2 = &g_xsh[((size_t)n*EC+65)*HW + p];  // max  -> shuffled ch 65
        m1[0]=psum.x*inv; m1[1]=psum.y*inv; m1[2]=psum.z*inv; m1[3]=psum.w*inv;
        m2[0]=pmax.x;     m2[1]=pmax.y;     m2[2]=pmax.z;     m2[3]=pmax.w;
    }
}

// ---------------- K2: multi-scale depthwise (3/5/7) + depthwise-3 pos-enc
//                  residual, fused per channel -----------------------------
__global__ __launch_bounds__(256) void k_branch_pe(
    const float* __restrict__ W3,const float* __restrict__ b3,
    const float* __restrict__ W5,const float* __restrict__ b5,
    const float* __restrict__ W7,const float* __restrict__ b7,
    const float* __restrict__ Wpe,const float* __restrict__ bpe)
{
    __shared__ float s0[38*38];
    __shared__ float s1[32*33];
    __shared__ float wsm[64];
    const int ch = blockIdx.x, n = blockIdx.y;
    const int t = threadIdx.x;
    int r; const float* Wb; float bb;
    if (ch < 22)      { r=1; Wb=W3+ch*9;       bb=b3[ch];    }
    else if (ch < 44) { r=2; Wb=W5+(ch-22)*25; bb=b5[ch-22]; }
    else              { r=3; Wb=W7+(ch-44)*49; bb=b7[ch-44]; }
    const int kw = 2*r+1, nw = kw*kw;
    if (t < nw) wsm[t] = Wb[t];
    if (t >= 49 && t < 58) wsm[t] = Wpe[ch*9 + t-49];
    const float bpev = bpe[ch];
    const float* in = g_xsh + ((size_t)n*EC+ch)*HW;
    for (int e=t; e<38*38; e+=256){
        const int sy = e/38 - 3, sx = e%38 - 3;
        s0[e] = (sy>=0 && sy<32 && sx>=0 && sx<32) ? in[sy*32+sx] : 0.f;
    }
    __syncthreads();
#pragma unroll
    for (int q=0;q<4;q++){
        const int p = t + q*256; const int y=p>>5, xx=p&31;
        float a = bb;
        for (int dy=-r; dy<=r; dy++)
            for (int dx=-r; dx<=r; dx++)
                a += wsm[(dy+r)*kw + dx+r] * s0[(y+3+dy)*38 + xx+3+dx];
        s1[y*33+xx] = a;
    }
    __syncthreads();
    float* out = g_xf2 + ((size_t)n*EC+ch)*HW;
#pragma unroll
    for (int q=0;q<4;q++){
        const int p = t + q*256; const int y=p>>5, xx=p&31;
        float a = bpev;
#pragma unroll
        for (int dy=-1; dy<=1; dy++){
            const int yy=y+dy;
#pragma unroll
            for (int dx=-1; dx<=1; dx++){
                const int xc=xx+dx;
                const float v = (yy>=0&&yy<32&&xc>=0&&xc<32) ? s1[yy*33+xc] : 0.f;
                a += wsm[49+(dy+1)*3+dx+1] * v;
            }
        }
        out[p] = s1[y*33+xx] + a;    // x_fused + pe-conv(x_fused)
    }
}

// ---------------- K3: LayerNorm(channels) + 3x3 conv 66->64 + GELU +
//                  residual(x64); 512 threads for 2x issue width ------------
__global__ __launch_bounds__(512) void k_mainconv(
    const float* __restrict__ lng, const float* __restrict__ lnb,
    const float* __restrict__ Wlast, const float* __restrict__ blast)
{
    __shared__ float sIn[EC*100];
    __shared__ float sg[EC], sb[EC];
    const int n = blockIdx.y;
    const int tile = blockIdx.x;
    const int ty0 = (tile>>2)*8, tx0 = (tile&3)*8;
    const int t = threadIdx.x;
    if (t < EC){ sg[t]=lng[t]; sb[t]=lnb[t]; }
    for (int e=t; e<EC*100; e+=512){
        const int c = e/100, rem = e-c*100, rr = rem/10, cc = rem-rr*10;
        const int gy = ty0-1+rr, gx = tx0-1+cc;
        sIn[e] = (gy>=0&&gy<32&&gx>=0&&gx<32) ?
                 g_xf2[((size_t)n*EC+c)*HW + gy*32+gx] : 0.f;
    }
    __syncthreads();
    if (t < 100){
        const int rr=t/10, cc=t-rr*10;
        const int gy=ty0-1+rr, gx=tx0-1+cc;
        if (gy>=0&&gy<32&&gx>=0&&gx<32){
            float s=0.f, sq=0.f;
#pragma unroll
            for (int c=0;c<EC;c++){ const float v=sIn[c*100+t]; s+=v; sq+=v*v; }
            const float mu = s*(1.f/66.f);
            const float var = sq*(1.f/66.f) - mu*mu;
            const float rs = rsqrtf(var + 1e-5f);
#pragma unroll
            for (int c=0;c<EC;c++)
                sIn[c*100+t] = (sIn[c*100+t]-mu)*rs*sg[c]+sb[c];
        }
    }
    __syncthreads();
    // 512 threads: oc = t>>3 (64), q = t&7 -> 2 rows x 4 cols per thread
    const int oc = t>>3, q = t&7;
    const int qy = (q>>1)*2, qx = (q&1)*4;
    const float bb = blast[oc];
    float acc[2][4];
#pragma unroll
    for (int i=0;i<2;i++)
#pragma unroll
        for (int j=0;j<4;j++) acc[i][j]=bb;
    const float* wl = Wlast + oc*EC*9;
    for (int c=0;c<EC;c++){
        float rIn[4][6];
        const int base = c*100 + qy*10 + qx;
#pragma unroll
        for (int i=0;i<4;i++)
#pragma unroll
            for (int j=0;j<6;j++) rIn[i][j] = sIn[base + i*10 + j];
        float w[9];
#pragma unroll
        for (int k=0;k<9;k++) w[k] = __ldg(wl + c*9 + k);
#pragma unroll
        for (int i=0;i<2;i++)
#pragma unroll
            for (int j=0;j<4;j++)
#pragma unroll
                for (int dy=0;dy<3;dy++)
#pragma unroll
                    for (int dx=0;dx<3;dx++)
                        acc[i][j] += w[dy*3+dx]*rIn[i+dy][j+dx];
    }
    const float* xr  = g_x64  + ((size_t)n*DC+oc)*HW;
    float*       out = g_out64 + ((size_t)n*DC+oc)*HW;
#pragma unroll
    for (int i=0;i<2;i++)
#pragma unroll
        for (int j=0;j<4;j++){
            const int p = (ty0+qy+i)*32 + tx0+qx+j;
            const float v = acc[i][j];
            const float ge = 0.5f*v*(1.f+erff(v*0.70710678118654752f));
            out[p] = ge + xr[p];
        }
}

// ---------------- K4: aux head dw3 -> dw5(dilation 3), fused per channel ---
__global__ __launch_bounds__(256) void k_aux(const float* __restrict__ Wa0,
                                             const float* __restrict__ Was)
{
    __shared__ float s0[34*34];
    __shared__ float s1[32*33];
    __shared__ float wsm[40];
    const int ch = blockIdx.x, n = blockIdx.y;
    const int t = threadIdx.x;
    if (t < 9)              wsm[t] = Wa0[ch*9+t];
    if (t >= 9 && t < 34)   wsm[t] = Was[ch*25 + t-9];
    const float* in = g_out64 + ((size_t)n*DC+ch)*HW;
    for (int e=t; e<34*34; e+=256){
        const int sy=e/34-1, sx=e%34-1;
        s0[e] = (sy>=0&&sy<32&&sx>=0&&sx<32)? in[sy*32+sx] : 0.f;
    }
    __syncthreads();
#pragma unroll
    for (int q=0;q<4;q++){
        const int p=t+q*256, y=p>>5, xx=p&31;
        float a=0.f;
#pragma unroll
        for (int dy=0;dy<3;dy++)
#pragma unroll
            for (int dx=0;dx<3;dx++)
                a += wsm[dy*3+dx]*s0[(y+dy)*34 + xx+dx];
        s1[y*33+xx]=a;
    }
    __syncthreads();
    float* out = g_tmp2 + ((size_t)n*DC+ch)*HW;
#pragma unroll
    for (int q=0;q<4;q++){
        const int p=t+q*256, y=p>>5, xx=p&31;
        float a=0.f;
#pragma unroll
        for (int ky=0;ky<5;ky++){
            const int yy = y + (ky-2)*3;
            if (yy<0||yy>=32) continue;
#pragma unroll
            for (int kx=0;kx<5;kx++){
                const int xc = xx + (kx-2)*3;
                if (xc<0||xc>=32) continue;
                a += wsm[9+ky*5+kx]*s1[yy*33+xc];
            }
        }
        out[p]=a;
    }
}

// ---------------- K5: 1x1 conv 64->6 ---------------------------------------
__global__ __launch_bounds__(256) void k_pw(const float* __restrict__ Wout)
{
    __shared__ float w[6*64];
    const int t = threadIdx.x;
    for (int i=t; i<384; i+=256) w[i] = Wout[i];
    __syncthreads();
    const int gp = blockIdx.x*256+t;
    const int n = gp>>10, p = gp&1023;
    const float* tp = g_tmp2 + (size_t)n*DC*HW + p;
    float acc[6]={0.f,0.f,0.f,0.f,0.f,0.f};
    for (int oc=0;oc<64;oc++){
        const float v = tp[(size_t)oc*HW];
#pragma unroll
        for (int k=0;k<6;k++) acc[k] += w[k*64+oc]*v;
    }
    float* f = g_feat + (size_t)n*6*HW + p;
#pragma unroll
    for (int k=0;k<6;k++) f[(size_t)k*HW] = acc[k];
}

// ---------------- K6: bilinear 32x32 -> 1024x1024 (half-pixel, clamped) ----
__global__ __launch_bounds__(256) void k_upsample(float* __restrict__ out)
{
    const int idx = blockIdx.x*256 + threadIdx.x;       // float4 units
    const int ox4 = idx & 255;
    const int oy  = (idx >> 8) & 1023;
    const int nk  = idx >> 18;
    if (nk >= NB*6) return;
    const float* f = g_feat + (size_t)nk*HW;

    const float sy = (oy + 0.5f)*0.03125f - 0.5f;
    const float fy = floorf(sy);
    const float wy = sy - fy;
    const int   iy = (int)fy;
    const int   y0 = min(max(iy,0),31);
    const int   y1 = min(iy+1,31);

    const int   ox0 = ox4*4;
    const float sx  = (ox0 + 0.5f)*0.03125f - 0.5f;
    const float fx  = floorf(sx);
    const float wx0 = sx - fx;
    const int   ix  = (int)fx;
    const int   x0  = min(max(ix,0),31);
    const int   x1  = min(ix+1,31);

    const float v00 = f[y0*32+x0], v01 = f[y0*32+x1];
    const float v10 = f[y1*32+x0], v11 = f[y1*32+x1];
    const float a = v00 + (v10-v00)*wy;
    const float b = v01 + (v11-v01)*wy;
    const float d = b - a;
    float4 o;
    o.x = a + d*wx0;
    o.y = a + d*(wx0+0.03125f);
    o.z = a + d*(wx0+0.0625f);
    o.w = a + d*(wx0+0.09375f);
    reinterpret_cast<float4*>(out)[idx] = o;
}

// ---------------- launch ----------------------------------------------------
extern "C" void kernel_launch(void* const* d_in, const int* in_sizes, int n_in,
                              void* d_out, int out_size)
{
    (void)out_size;
    const float *x=0,*W1=0,*b1=0,*W3=0,*b3=0,*W5=0,*b5=0,*W7=0,*b7=0;
    const float *Wpe=0,*bpe=0,*lng=0,*lnb=0,*Wlast=0,*blast=0,*Wa0=0,*Was=0,*Wout=0;
    int c22=0, c64=0, c66=0;
    for (int i=0;i<n_in;i++){
        const int s = in_sizes[i];
        const float* p = (const float*)d_in[i];
        switch (s){
            case 7274496: x=p; break;
            case 56832:   W1=p; break;
            case 198:     W3=p; break;
            case 550:     W5=p; break;
            case 1078:    W7=p; break;
            case 594:     Wpe=p; break;
            case 38016:   Wlast=p; break;
            case 576:     Wa0=p; break;
            case 1600:    Was=p; break;
            case 384:     Wout=p; break;
            case 64:      if (c64==0) b1=p; else blast=p; c64++; break;
            case 22:      if (c22==0) b3=p; else if (c22==1) b5=p; else b7=p; c22++; break;
            case 66:      if (c66==0) bpe=p; else if (c66==1) lng=p; else lnb=p; c66++; break;
            default: break; // h, w scalars
        }
    }

    k_gemm     <<<dim3(16,NB), 256>>>(x, W1, b1);
    k_branch_pe<<<dim3(EC,NB), 256>>>(W3,b3,W5,b5,W7,b7,Wpe,bpe);
    k_mainconv <<<dim3(16,NB), 512>>>(lng,lnb,Wlast,blast);
    k_aux      <<<dim3(DC,NB), 256>>>(Wa0,Was);
    k_pw       <<<32, 256>>>(Wout);
    k_upsample <<<(NB*6*1024*256)/256, 256>>>((float*)d_out);
}

// round 11
// speedup vs baseline: 1.2229x; 1.0798x over previous
#include <cuda_runtime.h>
#include <math.h>
#include <float.h>

#define NB   8
#define CIN  888
#define HW   1024
#define EC   66
#define DC   64

// ---------------- scratch (device globals; no allocation allowed) ----------
__device__ float g_x64  [NB*DC*HW];
__device__ float g_xsh  [NB*EC*HW];
__device__ float g_xf2  [NB*EC*HW];
__device__ float g_out64[NB*DC*HW];
__device__ float g_tmp2 [NB*DC*HW];
__device__ float g_feat [NB*6*HW];

__device__ __forceinline__ unsigned f2tf32(float f){
    unsigned u;
    asm("cvt.rna.tf32.f32 %0, %1;" : "=r"(u) : "f"(f));
    return u;
}

// ---------------- K1: 1x1 conv via TF32 mma.sync (64oc x 64px x 888k) +
//                  mean/max + channel-shuffle scatter -----------------------
// smem tiles transposed+padded: Xs[px][25], Ws[oc][25] (stride 25 = conflict-free)
__global__ __launch_bounds__(256) void k_gemm(const float* __restrict__ x,
                                              const float* __restrict__ W,
                                              const float* __restrict__ bias)
{
    __shared__ float Xs[2][64][25];
    __shared__ float Ws[2][64][25];
    __shared__ float redS[4][64];
    __shared__ float redM[4][64];

    const int n  = blockIdx.y;
    const int p0 = blockIdx.x * 64;
    const int t  = threadIdx.x;
    const int w    = t >> 5;
    const int lane = t & 31;
    const int lg   = lane >> 2;     // 0..7
    const int lk   = lane & 3;      // 0..3
    const int mrow0 = (w & 1) * 32;
    const int ncol0 = (w >> 1) * 16;
    const float* xn = x + (size_t)n*CIN*HW + p0;

    // mean/max partials: thread handles px = t&63, k-group = t>>6 (6 k each chunk)
    const int rpx = t & 63, rkg = t >> 6;
    float psum = 0.f, pmax = -FLT_MAX;

    float c[2][2][4];
#pragma unroll
    for (int mi=0;mi<2;mi++)
#pragma unroll
        for (int ni=0;ni<2;ni++)
#pragma unroll
            for (int k=0;k<4;k++) c[mi][ni][k]=0.f;

    // preload chunk 0 into buffer 0
#pragma unroll
    for (int i=0;i<6;i++){
        int e=t+i*256; int kk=e>>6, px=e&63;
        Xs[0][px][kk] = xn[kk*HW+px];
    }
#pragma unroll
    for (int i=0;i<6;i++){
        int e=t+i*256; int oc=e/24, kk=e-oc*24;
        Ws[0][oc][kk] = W[oc*CIN+kk];
    }
    __syncthreads();

    for (int ch=0; ch<37; ch++){
        const int cur = ch & 1;
        // prefetch next chunk into the other buffer
        if (ch < 36){
            const int k0 = (ch+1)*24;
            const int nxt = cur ^ 1;
#pragma unroll
            for (int i=0;i<6;i++){
                int e=t+i*256; int kk=e>>6, px=e&63;
                Xs[nxt][px][kk] = xn[(k0+kk)*HW+px];
            }
#pragma unroll
            for (int i=0;i<6;i++){
                int e=t+i*256; int oc=e/24, kk=e-oc*24;
                Ws[nxt][oc][kk] = W[oc*CIN+k0+kk];
            }
        }
        // mean/max partials on current X tile
#pragma unroll
        for (int k=0;k<6;k++){
            const float v = Xs[cur][rpx][rkg*6+k];
            psum += v;
            pmax = fmaxf(pmax, v);
        }
        // 3 k-steps of 8
#pragma unroll
        for (int ks=0; ks<3; ks++){
            const int kb = ks*8;
            unsigned a[2][4], b[2][2];
#pragma unroll
            for (int mi=0;mi<2;mi++){
                const int r = mrow0 + mi*16 + lg;
                a[mi][0] = f2tf32(Ws[cur][r  ][kb+lk  ]);
                a[mi][1] = f2tf32(Ws[cur][r+8][kb+lk  ]);
                a[mi][2] = f2tf32(Ws[cur][r  ][kb+lk+4]);
                a[mi][3] = f2tf32(Ws[cur][r+8][kb+lk+4]);
            }
#pragma unroll
            for (int ni=0;ni<2;ni++){
                const int cpx = ncol0 + ni*8 + lg;
                b[ni][0] = f2tf32(Xs[cur][cpx][kb+lk  ]);
                b[ni][1] = f2tf32(Xs[cur][cpx][kb+lk+4]);
            }
#pragma unroll
            for (int mi=0;mi<2;mi++)
#pragma unroll
                for (int ni=0;ni<2;ni++){
                    asm volatile(
                        "mma.sync.aligned.m16n8k8.row.col.f32.tf32.tf32.f32 "
                        "{%0,%1,%2,%3}, {%4,%5,%6,%7}, {%8,%9}, {%0,%1,%2,%3};"
                        : "+f"(c[mi][ni][0]),"+f"(c[mi][ni][1]),
                          "+f"(c[mi][ni][2]),"+f"(c[mi][ni][3])
                        : "r"(a[mi][0]),"r"(a[mi][1]),"r"(a[mi][2]),"r"(a[mi][3]),
                          "r"(b[ni][0]),"r"(b[ni][1]));
                }
        }
        __syncthreads();
    }

    // ---- mean/max final reduce ----
    redS[rkg][rpx] = psum;
    redM[rkg][rpx] = pmax;
    __syncthreads();
    if (t < 64){
        const float s = redS[0][t]+redS[1][t]+redS[2][t]+redS[3][t];
        const float m = fmaxf(fmaxf(redM[0][t],redM[1][t]),
                              fmaxf(redM[2][t],redM[3][t]));
        const int p = p0 + t;
        g_xsh[((size_t)n*EC+43)*HW + p] = s * (1.f/888.f);  // mean -> shuffled ch43
        g_xsh[((size_t)n*EC+65)*HW + p] = m;                 // max  -> shuffled ch65
    }

    // ---- epilogue: bias + scatter (direct + shuffled) ----
#pragma unroll
    for (int mi=0;mi<2;mi++){
#pragma unroll
        for (int half=0; half<2; half++){
            const int oc = mrow0 + mi*16 + lg + half*8;
            const float bb = __ldg(&bias[oc]);
            const int sc = (oc%3)*22 + oc/3;
            float* d1 = &g_x64[((size_t)n*DC+oc)*HW];
            float* d2 = &g_xsh[((size_t)n*EC+sc)*HW];
#pragma unroll
            for (int ni=0;ni<2;ni++){
                const int col = ncol0 + ni*8 + lk*2;
                const float v0 = c[mi][ni][half*2+0] + bb;
                const float v1 = c[mi][ni][half*2+1] + bb;
                d1[p0+col]   = v0; d1[p0+col+1] = v1;
                d2[p0+col]   = v0; d2[p0+col+1] = v1;
            }
        }
    }
}

// ---------------- K2: multi-scale depthwise (3/5/7) + depthwise-3 pos-enc
//                  residual, fused per channel -----------------------------
__global__ __launch_bounds__(256) void k_branch_pe(
    const float* __restrict__ W3,const float* __restrict__ b3,
    const float* __restrict__ W5,const float* __restrict__ b5,
    const float* __restrict__ W7,const float* __restrict__ b7,
    const float* __restrict__ Wpe,const float* __restrict__ bpe)
{
    __shared__ float s0[38*38];
    __shared__ float s1[32*33];
    __shared__ float wsm[64];
    const int ch = blockIdx.x, n = blockIdx.y;
    const int t = threadIdx.x;
    int r; const float* Wb; float bb;
    if (ch < 22)      { r=1; Wb=W3+ch*9;       bb=b3[ch];    }
    else if (ch < 44) { r=2; Wb=W5+(ch-22)*25; bb=b5[ch-22]; }
    else              { r=3; Wb=W7+(ch-44)*49; bb=b7[ch-44]; }
    const int kw = 2*r+1, nw = kw*kw;
    if (t < nw) wsm[t] = Wb[t];
    if (t >= 49 && t < 58) wsm[t] = Wpe[ch*9 + t-49];
    const float bpev = bpe[ch];
    const float* in = g_xsh + ((size_t)n*EC+ch)*HW;
    for (int e=t; e<38*38; e+=256){
        const int sy = e/38 - 3, sx = e%38 - 3;
        s0[e] = (sy>=0 && sy<32 && sx>=0 && sx<32) ? in[sy*32+sx] : 0.f;
    }
    __syncthreads();
#pragma unroll
    for (int q=0;q<4;q++){
        const int p = t + q*256; const int y=p>>5, xx=p&31;
        float a = bb;
        for (int dy=-r; dy<=r; dy++)
            for (int dx=-r; dx<=r; dx++)
                a += wsm[(dy+r)*kw + dx+r] * s0[(y+3+dy)*38 + xx+3+dx];
        s1[y*33+xx] = a;
    }
    __syncthreads();
    float* out = g_xf2 + ((size_t)n*EC+ch)*HW;
#pragma unroll
    for (int q=0;q<4;q++){
        const int p = t + q*256; const int y=p>>5, xx=p&31;
        float a = bpev;
#pragma unroll
        for (int dy=-1; dy<=1; dy++){
            const int yy=y+dy;
#pragma unroll
            for (int dx=-1; dx<=1; dx++){
                const int xc=xx+dx;
                const float v = (yy>=0&&yy<32&&xc>=0&&xc<32) ? s1[yy*33+xc] : 0.f;
                a += wsm[49+(dy+1)*3+dx+1] * v;
            }
        }
        out[p] = s1[y*33+xx] + a;    // x_fused + pe-conv(x_fused)
    }
}

// ---------------- K3: LayerNorm(channels) + 3x3 conv 66->64 + GELU +
//                  residual(x64); 512 threads -------------------------------
__global__ __launch_bounds__(512) void k_mainconv(
    const float* __restrict__ lng, const float* __restrict__ lnb,
    const float* __restrict__ Wlast, const float* __restrict__ blast)
{
    __shared__ float sIn[EC*100];
    __shared__ float sg[EC], sb[EC];
    const int n = blockIdx.y;
    const int tile = blockIdx.x;
    const int ty0 = (tile>>2)*8, tx0 = (tile&3)*8;
    const int t = threadIdx.x;
    if (t < EC){ sg[t]=lng[t]; sb[t]=lnb[t]; }
    for (int e=t; e<EC*100; e+=512){
        const int c = e/100, rem = e-c*100, rr = rem/10, cc = rem-rr*10;
        const int gy = ty0-1+rr, gx = tx0-1+cc;
        sIn[e] = (gy>=0&&gy<32&&gx>=0&&gx<32) ?
                 g_xf2[((size_t)n*EC+c)*HW + gy*32+gx] : 0.f;
    }
    __syncthreads();
    if (t < 100){
        const int rr=t/10, cc=t-rr*10;
        const int gy=ty0-1+rr, gx=tx0-1+cc;
        if (gy>=0&&gy<32&&gx>=0&&gx<32){
            float s=0.f, sq=0.f;
#pragma unroll
            for (int c=0;c<EC;c++){ const float v=sIn[c*100+t]; s+=v; sq+=v*v; }
            const float mu = s*(1.f/66.f);
            const float var = sq*(1.f/66.f) - mu*mu;
            const float rs = rsqrtf(var + 1e-5f);
#pragma unroll
            for (int c=0;c<EC;c++)
                sIn[c*100+t] = (sIn[c*100+t]-mu)*rs*sg[c]+sb[c];
        }
    }
    __syncthreads();
    const int oc = t>>3, q = t&7;
    const int qy = (q>>1)*2, qx = (q&1)*4;
    const float bb = blast[oc];
    float acc[2][4];
#pragma unroll
    for (int i=0;i<2;i++)
#pragma unroll
        for (int j=0;j<4;j++) acc[i][j]=bb;
    const float* wl = Wlast + oc*EC*9;
    for (int c=0;c<EC;c++){
        float rIn[4][6];
        const int base = c*100 + qy*10 + qx;
#pragma unroll
        for (int i=0;i<4;i++)
#pragma unroll
            for (int j=0;j<6;j++) rIn[i][j] = sIn[base + i*10 + j];
        float w[9];
#pragma unroll
        for (int k=0;k<9;k++) w[k] = __ldg(wl + c*9 + k);
#pragma unroll
        for (int i=0;i<2;i++)
#pragma unroll
            for (int j=0;j<4;j++)
#pragma unroll
                for (int dy=0;dy<3;dy++)
#pragma unroll
                    for (int dx=0;dx<3;dx++)
                        acc[i][j] += w[dy*3+dx]*rIn[i+dy][j+dx];
    }
    const float* xr  = g_x64  + ((size_t)n*DC+oc)*HW;
    float*       out = g_out64 + ((size_t)n*DC+oc)*HW;
#pragma unroll
    for (int i=0;i<2;i++)
#pragma unroll
        for (int j=0;j<4;j++){
            const int p = (ty0+qy+i)*32 + tx0+qx+j;
            const float v = acc[i][j];
            const float ge = 0.5f*v*(1.f+erff(v*0.70710678118654752f));
            out[p] = ge + xr[p];
        }
}

// ---------------- K4: aux head dw3 -> dw5(dilation 3), fused per channel ---
__global__ __launch_bounds__(256) void k_aux(const float* __restrict__ Wa0,
                                             const float* __restrict__ Was)
{
    __shared__ float s0[34*34];
    __shared__ float s1[32*33];
    __shared__ float wsm[40];
    const int ch = blockIdx.x, n = blockIdx.y;
    const int t = threadIdx.x;
    if (t < 9)              wsm[t] = Wa0[ch*9+t];
    if (t >= 9 && t < 34)   wsm[t] = Was[ch*25 + t-9];
    const float* in = g_out64 + ((size_t)n*DC+ch)*HW;
    for (int e=t; e<34*34; e+=256){
        const int sy=e/34-1, sx=e%34-1;
        s0[e] = (sy>=0&&sy<32&&sx>=0&&sx<32)? in[sy*32+sx] : 0.f;
    }
    __syncthreads();
#pragma unroll
    for (int q=0;q<4;q++){
        const int p=t+q*256, y=p>>5, xx=p&31;
        float a=0.f;
#pragma unroll
        for (int dy=0;dy<3;dy++)
#pragma unroll
            for (int dx=0;dx<3;dx++)
                a += wsm[dy*3+dx]*s0[(y+dy)*34 + xx+dx];
        s1[y*33+xx]=a;
    }
    __syncthreads();
    float* out = g_tmp2 + ((size_t)n*DC+ch)*HW;
#pragma unroll
    for (int q=0;q<4;q++){
        const int p=t+q*256, y=p>>5, xx=p&31;
        float a=0.f;
#pragma unroll
        for (int ky=0;ky<5;ky++){
            const int yy = y + (ky-2)*3;
            if (yy<0||yy>=32) continue;
#pragma unroll
            for (int kx=0;kx<5;kx++){
                const int xc = xx + (kx-2)*3;
                if (xc<0||xc>=32) continue;
                a += wsm[9+ky*5+kx]*s1[yy*33+xc];
            }
        }
        out[p]=a;
    }
}

// ---------------- K5: 1x1 conv 64->6 ---------------------------------------
__global__ __launch_bounds__(256) void k_pw(const float* __restrict__ Wout)
{
    __shared__ float w[6*64];
    const int t = threadIdx.x;
    for (int i=t; i<384; i+=256) w[i] = Wout[i];
    __syncthreads();
    const int gp = blockIdx.x*256+t;
    const int n = gp>>10, p = gp&1023;
    const float* tp = g_tmp2 + (size_t)n*DC*HW + p;
    float acc[6]={0.f,0.f,0.f,0.f,0.f,0.f};
    for (int oc=0;oc<64;oc++){
        const float v = tp[(size_t)oc*HW];
#pragma unroll
        for (int k=0;k<6;k++) acc[k] += w[k*64+oc]*v;
    }
    float* f = g_feat + (size_t)n*6*HW + p;
#pragma unroll
    for (int k=0;k<6;k++) f[(size_t)k*HW] = acc[k];
}

// ---------------- K6: bilinear 32x32 -> 1024x1024 (half-pixel, clamped) ----
__global__ __launch_bounds__(256) void k_upsample(float* __restrict__ out)
{
    const int idx = blockIdx.x*256 + threadIdx.x;       // float4 units
    const int ox4 = idx & 255;
    const int oy  = (idx >> 8) & 1023;
    const int nk  = idx >> 18;
    if (nk >= NB*6) return;
    const float* f = g_feat + (size_t)nk*HW;

    const float sy = (oy + 0.5f)*0.03125f - 0.5f;
    const float fy = floorf(sy);
    const float wy = sy - fy;
    const int   iy = (int)fy;
    const int   y0 = min(max(iy,0),31);
    const int   y1 = min(iy+1,31);

    const int   ox0 = ox4*4;
    const float sx  = (ox0 + 0.5f)*0.03125f - 0.5f;
    const float fx  = floorf(sx);
    const float wx0 = sx - fx;
    const int   ix  = (int)fx;
    const int   x0  = min(max(ix,0),31);
    const int   x1  = min(ix+1,31);

    const float v00 = f[y0*32+x0], v01 = f[y0*32+x1];
    const float v10 = f[y1*32+x0], v11 = f[y1*32+x1];
    const float a = v00 + (v10-v00)*wy;
    const float b = v01 + (v11-v01)*wy;
    const float d = b - a;
    float4 o;
    o.x = a + d*wx0;
    o.y = a + d*(wx0+0.03125f);
    o.z = a + d*(wx0+0.0625f);
    o.w = a + d*(wx0+0.09375f);
    reinterpret_cast<float4*>(out)[idx] = o;
}

// ---------------- launch ----------------------------------------------------
extern "C" void kernel_launch(void* const* d_in, const int* in_sizes, int n_in,
                              void* d_out, int out_size)
{
    (void)out_size;
    const float *x=0,*W1=0,*b1=0,*W3=0,*b3=0,*W5=0,*b5=0,*W7=0,*b7=0;
    const float *Wpe=0,*bpe=0,*lng=0,*lnb=0,*Wlast=0,*blast=0,*Wa0=0,*Was=0,*Wout=0;
    int c22=0, c64=0, c66=0;
    for (int i=0;i<n_in;i++){
        const int s = in_sizes[i];
        const float* p = (const float*)d_in[i];
        switch (s){
            case 7274496: x=p; break;
            case 56832:   W1=p; break;
            case 198:     W3=p; break;
            case 550:     W5=p; break;
            case 1078:    W7=p; break;
            case 594:     Wpe=p; break;
            case 38016:   Wlast=p; break;
            case 576:     Wa0=p; break;
            case 1600:    Was=p; break;
            case 384:     Wout=p; break;
            case 64:      if (c64==0) b1=p; else blast=p; c64++; break;
            case 22:      if (c22==0) b3=p; else if (c22==1) b5=p; else b7=p; c22++; break;
            case 66:      if (c66==0) bpe=p; else if (c66==1) lng=p; else lnb=p; c66++; break;
            default: break; // h, w scalars
        }
    }

    k_gemm     <<<dim3(16,NB), 256>>>(x, W1, b1);
    k_branch_pe<<<dim3(EC,NB), 256>>>(W3,b3,W5,b5,W7,b7,Wpe,bpe);
    k_mainconv <<<dim3(16,NB), 512>>>(lng,lnb,Wlast,blast);
    k_aux      <<<dim3(DC,NB), 256>>>(Wa0,Was);
    k_pw       <<<32, 256>>>(Wout);
    k_upsample <<<(NB*6*1024*256)/256, 256>>>((float*)d_out);
}

// round 14
// speedup vs baseline: 1.7097x; 1.3980x over previous
#include <cuda_runtime.h>
#include <math.h>
#include <float.h>

#define NB   8
#define CIN  888
#define HW   1024
#define EC   66
#define DC   64

// ---------------- scratch (device globals; no allocation allowed) ----------
__device__ float g_x64  [NB*DC*HW];
__device__ float g_xsh  [NB*EC*HW];
__device__ float g_xf2  [NB*EC*HW];
__device__ float g_out64[NB*DC*HW];
__device__ float g_tmp2 [NB*DC*HW];
__device__ float g_feat [NB*6*HW];

__device__ __forceinline__ unsigned f2tf32(float f){
    unsigned u;
    asm("cvt.rna.tf32.f32 %0, %1;" : "=r"(u) : "f"(f));
    return u;
}

// ---------------- K1: 1x1 conv via TF32 mma.sync (64oc x 64px x 888k) +
//                  mean/max + channel-shuffle scatter -----------------------
__global__ __launch_bounds__(256) void k_gemm(const float* __restrict__ x,
                                              const float* __restrict__ W,
                                              const float* __restrict__ bias)
{
    __shared__ float Xs[2][64][25];
    __shared__ float Ws[2][64][25];
    __shared__ float redS[4][64];
    __shared__ float redM[4][64];

    const int n  = blockIdx.y;
    const int p0 = blockIdx.x * 64;
    const int t  = threadIdx.x;
    const int w    = t >> 5;
    const int lane = t & 31;
    const int lg   = lane >> 2;
    const int lk   = lane & 3;
    const int mrow0 = (w & 1) * 32;
    const int ncol0 = (w >> 1) * 16;
    const float* xn = x + (size_t)n*CIN*HW + p0;

    const int rpx = t & 63, rkg = t >> 6;
    float psum = 0.f, pmax = -FLT_MAX;

    float c[2][2][4];
#pragma unroll
    for (int mi=0;mi<2;mi++)
#pragma unroll
        for (int ni=0;ni<2;ni++)
#pragma unroll
            for (int k=0;k<4;k++) c[mi][ni][k]=0.f;

#pragma unroll
    for (int i=0;i<6;i++){
        int e=t+i*256; int kk=e>>6, px=e&63;
        Xs[0][px][kk] = xn[kk*HW+px];
    }
#pragma unroll
    for (int i=0;i<6;i++){
        int e=t+i*256; int oc=e/24, kk=e-oc*24;
        Ws[0][oc][kk] = W[oc*CIN+kk];
    }
    __syncthreads();

    for (int ch=0; ch<37; ch++){
        const int cur = ch & 1;
        if (ch < 36){
            const int k0 = (ch+1)*24;
            const int nxt = cur ^ 1;
#pragma unroll
            for (int i=0;i<6;i++){
                int e=t+i*256; int kk=e>>6, px=e&63;
                Xs[nxt][px][kk] = xn[(k0+kk)*HW+px];
            }
#pragma unroll
            for (int i=0;i<6;i++){
                int e=t+i*256; int oc=e/24, kk=e-oc*24;
                Ws[nxt][oc][kk] = W[oc*CIN+k0+kk];
            }
        }
#pragma unroll
        for (int k=0;k<6;k++){
            const float v = Xs[cur][rpx][rkg*6+k];
            psum += v;
            pmax = fmaxf(pmax, v);
        }
#pragma unroll
        for (int ks=0; ks<3; ks++){
            const int kb = ks*8;
            unsigned a[2][4], b[2][2];
#pragma unroll
            for (int mi=0;mi<2;mi++){
                const int r = mrow0 + mi*16 + lg;
                a[mi][0] = f2tf32(Ws[cur][r  ][kb+lk  ]);
                a[mi][1] = f2tf32(Ws[cur][r+8][kb+lk  ]);
                a[mi][2] = f2tf32(Ws[cur][r  ][kb+lk+4]);
                a[mi][3] = f2tf32(Ws[cur][r+8][kb+lk+4]);
            }
#pragma unroll
            for (int ni=0;ni<2;ni++){
                const int cpx = ncol0 + ni*8 + lg;
                b[ni][0] = f2tf32(Xs[cur][cpx][kb+lk  ]);
                b[ni][1] = f2tf32(Xs[cur][cpx][kb+lk+4]);
            }
#pragma unroll
            for (int mi=0;mi<2;mi++)
#pragma unroll
                for (int ni=0;ni<2;ni++){
                    asm volatile(
                        "mma.sync.aligned.m16n8k8.row.col.f32.tf32.tf32.f32 "
                        "{%0,%1,%2,%3}, {%4,%5,%6,%7}, {%8,%9}, {%0,%1,%2,%3};"
                        : "+f"(c[mi][ni][0]),"+f"(c[mi][ni][1]),
                          "+f"(c[mi][ni][2]),"+f"(c[mi][ni][3])
                        : "r"(a[mi][0]),"r"(a[mi][1]),"r"(a[mi][2]),"r"(a[mi][3]),
                          "r"(b[ni][0]),"r"(b[ni][1]));
                }
        }
        __syncthreads();
    }

    redS[rkg][rpx] = psum;
    redM[rkg][rpx] = pmax;
    __syncthreads();
    if (t < 64){
        const float s = redS[0][t]+redS[1][t]+redS[2][t]+redS[3][t];
        const float m = fmaxf(fmaxf(redM[0][t],redM[1][t]),
                              fmaxf(redM[2][t],redM[3][t]));
        const int p = p0 + t;
        g_xsh[((size_t)n*EC+43)*HW + p] = s * (1.f/888.f);
        g_xsh[((size_t)n*EC+65)*HW + p] = m;
    }

#pragma unroll
    for (int mi=0;mi<2;mi++){
#pragma unroll
        for (int half=0; half<2; half++){
            const int oc = mrow0 + mi*16 + lg + half*8;
            const float bb = __ldg(&bias[oc]);
            const int sc = (oc%3)*22 + oc/3;
            float* d1 = &g_x64[((size_t)n*DC+oc)*HW];
            float* d2 = &g_xsh[((size_t)n*EC+sc)*HW];
#pragma unroll
            for (int ni=0;ni<2;ni++){
                const int col = ncol0 + ni*8 + lk*2;
                const float v0 = c[mi][ni][half*2+0] + bb;
                const float v1 = c[mi][ni][half*2+1] + bb;
                d1[p0+col]   = v0; d1[p0+col+1] = v1;
                d2[p0+col]   = v0; d2[p0+col+1] = v1;
            }
        }
    }
}

// ---------------- K2: multi-scale depthwise (3/5/7) + depthwise-3 pos-enc
//                  residual, fused per channel -----------------------------
__global__ __launch_bounds__(256) void k_branch_pe(
    const float* __restrict__ W3,const float* __restrict__ b3,
    const float* __restrict__ W5,const float* __restrict__ b5,
    const float* __restrict__ W7,const float* __restrict__ b7,
    const float* __restrict__ Wpe,const float* __restrict__ bpe)
{
    __shared__ float s0[38*38];
    __shared__ float s1[32*33];
    __shared__ float wsm[64];
    const int ch = blockIdx.x, n = blockIdx.y;
    const int t = threadIdx.x;
    int r; const float* Wb; float bb;
    if (ch < 22)      { r=1; Wb=W3+ch*9;       bb=b3[ch];    }
    else if (ch < 44) { r=2; Wb=W5+(ch-22)*25; bb=b5[ch-22]; }
    else              { r=3; Wb=W7+(ch-44)*49; bb=b7[ch-44]; }
    const int kw = 2*r+1, nw = kw*kw;
    if (t < nw) wsm[t] = Wb[t];
    if (t >= 49 && t < 58) wsm[t] = Wpe[ch*9 + t-49];
    const float bpev = bpe[ch];
    const float* in = g_xsh + ((size_t)n*EC+ch)*HW;
    for (int e=t; e<38*38; e+=256){
        const int sy = e/38 - 3, sx = e%38 - 3;
        s0[e] = (sy>=0 && sy<32 && sx>=0 && sx<32) ? in[sy*32+sx] : 0.f;
    }
    __syncthreads();
#pragma unroll
    for (int q=0;q<4;q++){
        const int p = t + q*256; const int y=p>>5, xx=p&31;
        float a = bb;
        for (int dy=-r; dy<=r; dy++)
            for (int dx=-r; dx<=r; dx++)
                a += wsm[(dy+r)*kw + dx+r] * s0[(y+3+dy)*38 + xx+3+dx];
        s1[y*33+xx] = a;
    }
    __syncthreads();
    float* out = g_xf2 + ((size_t)n*EC+ch)*HW;
#pragma unroll
    for (int q=0;q<4;q++){
        const int p = t + q*256; const int y=p>>5, xx=p&31;
        float a = bpev;
#pragma unroll
        for (int dy=-1; dy<=1; dy++){
            const int yy=y+dy;
#pragma unroll
            for (int dx=-1; dx<=1; dx++){
                const int xc=xx+dx;
                const float v = (yy>=0&&yy<32&&xc>=0&&xc<32) ? s1[yy*33+xc] : 0.f;
                a += wsm[49+(dy+1)*3+dx+1] * v;
            }
        }
        out[p] = s1[y*33+xx] + a;
    }
}

// ---------------- K3: LayerNorm(channels) + 3x3 conv 66->64 via TF32 mma +
//                  GELU + residual(x64) -------------------------------------
// block = 2 rows x 32 cols (64 px) x all 64 oc; grid (16, NB)
__global__ __launch_bounds__(256) void k_mainconv(
    const float* __restrict__ lng, const float* __restrict__ lnb,
    const float* __restrict__ Wlast, const float* __restrict__ blast)
{
    __shared__ float sLn[72][4][36];   // [chan pad 72][halo row 4][halo col 34 pad 36]
    __shared__ float sA[64][25];       // weight sub-tile: 64 oc x 24 k (pad 25)
    __shared__ float sg[EC], sb[EC];

    const int n  = blockIdx.y;
    const int ty = blockIdx.x;          // output rows 2ty, 2ty+1
    const int t  = threadIdx.x;
    const int w    = t >> 5;
    const int lane = t & 31;
    const int lg   = lane >> 2;
    const int lk   = lane & 3;
    const int mrow0 = (w & 1) * 32;     // oc
    const int ncol0 = (w >> 1) * 16;    // px

    if (t < EC){ sg[t]=lng[t]; sb[t]=lnb[t]; }
    // zero padding channels 66..71 (rows 0..3, cols 0..35)
    for (int e=t; e<6*4*36; e+=256){
        const int cc=e/(4*36), rem=e%(4*36);
        sLn[66+cc][rem/36][rem%36] = 0.f;
    }
    // load halo: 66 channels x 4 rows x 34 cols (zero outside image)
    for (int e=t; e<EC*136; e+=256){
        const int cch=e/136, rem=e%136, rr=rem/34, cc=rem%34;
        const int gy = 2*ty-1+rr, gx = cc-1;
        sLn[cch][rr][cc] = (gy>=0&&gy<32&&gx>=0&&gx<32) ?
            g_xf2[((size_t)n*EC+cch)*HW + gy*32+gx] : 0.f;
    }
    __syncthreads();
    // LayerNorm per halo pixel over 66 channels, store tf32-rounded bits
    if (t < 136){
        const int rr=t/34, cc=t%34;
        const int gy=2*ty-1+rr, gx=cc-1;
        if (gy>=0&&gy<32&&gx>=0&&gx<32){
            float s=0.f, sq=0.f;
#pragma unroll
            for (int cch=0;cch<EC;cch++){ const float v=sLn[cch][rr][cc]; s+=v; sq+=v*v; }
            const float mu = s*(1.f/66.f);
            const float var = sq*(1.f/66.f) - mu*mu;
            const float rs = rsqrtf(var + 1e-5f);
#pragma unroll
            for (int cch=0;cch<EC;cch++)
                sLn[cch][rr][cc] = __uint_as_float(
                    f2tf32((sLn[cch][rr][cc]-mu)*rs*sg[cch]+sb[cch]));
        } else {
            // zero is exact in tf32; nothing to do
        }
    }

    float c[2][2][4];
#pragma unroll
    for (int mi=0;mi<2;mi++)
#pragma unroll
        for (int ni=0;ni<2;ni++)
#pragma unroll
            for (int k=0;k<4;k++) c[mi][ni][k]=0.f;

    // K = 72 chan x 9 taps = 648, chunked: 9 chan-chunks x 3 sub-tiles x 3 ksteps
    for (int ch8=0; ch8<9; ch8++){
        for (int sub=0; sub<3; sub++){
            __syncthreads();
            // load A sub-tile 64x24, pre-converted to tf32
#pragma unroll
            for (int i=0;i<6;i++){
                const int e=t+i*256;         // < 1536
                const int oc=e/24, kl=e%24;
                const int klc = sub*24+kl;   // 0..71 within chunk
                const int cg = ch8*8 + klc/9, off = klc%9;
                sA[oc][kl] = (cg<EC) ?
                    __uint_as_float(f2tf32(Wlast[oc*EC*9 + cg*9 + off])) : 0.f;
            }
            __syncthreads();
#pragma unroll
            for (int ks=0; ks<3; ks++){
                const int kbl = ks*8;          // A-local k base
                const int kbg = sub*24 + kbl;  // chunk-local k base (for B)
                unsigned a[2][4];
#pragma unroll
                for (int mi=0;mi<2;mi++){
                    const int r = mrow0 + mi*16 + lg;
                    a[mi][0] = __float_as_uint(sA[r  ][kbl+lk  ]);
                    a[mi][1] = __float_as_uint(sA[r+8][kbl+lk  ]);
                    a[mi][2] = __float_as_uint(sA[r  ][kbl+lk+4]);
                    a[mi][3] = __float_as_uint(sA[r+8][kbl+lk+4]);
                }
                const int k1 = kbg+lk, k2 = kbg+lk+4;
                const int c1 = k1/9, o1 = k1-9*c1;
                const int c2 = k2/9, o2 = k2-9*c2;
                const int dy1 = o1/3, dx1 = o1-3*dy1;
                const int dy2 = o2/3, dx2 = o2-3*dy2;
                const int cg1 = ch8*8+c1, cg2 = ch8*8+c2;
                unsigned b[2][2];
#pragma unroll
                for (int ni=0;ni<2;ni++){
                    const int cpx = ncol0 + ni*8 + lg;
                    const int row = cpx>>5, col = cpx&31;
                    b[ni][0] = __float_as_uint(sLn[cg1][row+dy1][col+dx1]);
                    b[ni][1] = __float_as_uint(sLn[cg2][row+dy2][col+dx2]);
                }
#pragma unroll
                for (int mi=0;mi<2;mi++)
#pragma unroll
                    for (int ni=0;ni<2;ni++){
                        asm volatile(
                            "mma.sync.aligned.m16n8k8.row.col.f32.tf32.tf32.f32 "
                            "{%0,%1,%2,%3}, {%4,%5,%6,%7}, {%8,%9}, {%0,%1,%2,%3};"
                            : "+f"(c[mi][ni][0]),"+f"(c[mi][ni][1]),
                              "+f"(c[mi][ni][2]),"+f"(c[mi][ni][3])
                            : "r"(a[mi][0]),"r"(a[mi][1]),"r"(a[mi][2]),"r"(a[mi][3]),
                              "r"(b[ni][0]),"r"(b[ni][1]));
                    }
            }
        }
    }

    // epilogue: bias + GELU(exact) + residual
#pragma unroll
    for (int mi=0;mi<2;mi++){
#pragma unroll
        for (int half=0; half<2; half++){
            const int oc = mrow0 + mi*16 + lg + half*8;
            const float bb = __ldg(&blast[oc]);
            const float* xr  = g_x64  + ((size_t)n*DC+oc)*HW;
            float*       out = g_out64 + ((size_t)n*DC+oc)*HW;
#pragma unroll
            for (int ni=0;ni<2;ni++){
                const int colt = ncol0 + ni*8 + lk*2;
#pragma unroll
                for (int u=0;u<2;u++){
                    const int px = colt+u;
                    const int p = (2*ty + (px>>5))*32 + (px&31);
                    const float v = c[mi][ni][half*2+u] + bb;
                    const float ge = 0.5f*v*(1.f+erff(v*0.70710678118654752f));
                    out[p] = ge + xr[p];
                }
            }
        }
    }
}

// ---------------- K4: aux head dw3 -> dw5(dilation 3), fused per channel ---
__global__ __launch_bounds__(256) void k_aux(const float* __restrict__ Wa0,
                                             const float* __restrict__ Was)
{
    __shared__ float s0[34*34];
    __shared__ float s1[32*33];
    __shared__ float wsm[40];
    const int ch = blockIdx.x, n = blockIdx.y;
    const int t = threadIdx.x;
    if (t < 9)              wsm[t] = Wa0[ch*9+t];
    if (t >= 9 && t < 34)   wsm[t] = Was[ch*25 + t-9];
    const float* in = g_out64 + ((size_t)n*DC+ch)*HW;
    for (int e=t; e<34*34; e+=256){
        const int sy=e/34-1, sx=e%34-1;
        s0[e] = (sy>=0&&sy<32&&sx>=0&&sx<32)? in[sy*32+sx] : 0.f;
    }
    __syncthreads();
#pragma unroll
    for (int q=0;q<4;q++){
        const int p=t+q*256, y=p>>5, xx=p&31;
        float a=0.f;
#pragma unroll
        for (int dy=0;dy<3;dy++)
#pragma unroll
            for (int dx=0;dx<3;dx++)
                a += wsm[dy*3+dx]*s0[(y+dy)*34 + xx+dx];
        s1[y*33+xx]=a;
    }
    __syncthreads();
    float* out = g_tmp2 + ((size_t)n*DC+ch)*HW;
#pragma unroll
    for (int q=0;q<4;q++){
        const int p=t+q*256, y=p>>5, xx=p&31;
        float a=0.f;
#pragma unroll
        for (int ky=0;ky<5;ky++){
            const int yy = y + (ky-2)*3;
            if (yy<0||yy>=32) continue;
#pragma unroll
            for (int kx=0;kx<5;kx++){
                const int xc = xx + (kx-2)*3;
                if (xc<0||xc>=32) continue;
                a += wsm[9+ky*5+kx]*s1[yy*33+xc];
            }
        }
        out[p]=a;
    }
}

// ---------------- K5: 1x1 conv 64->6 ---------------------------------------
__global__ __launch_bounds__(256) void k_pw(const float* __restrict__ Wout)
{
    __shared__ float w[6*64];
    const int t = threadIdx.x;
    for (int i=t; i<384; i+=256) w[i] = Wout[i];
    __syncthreads();
    const int gp = blockIdx.x*256+t;
    const int n = gp>>10, p = gp&1023;
    const float* tp = g_tmp2 + (size_t)n*DC*HW + p;
    float acc[6]={0.f,0.f,0.f,0.f,0.f,0.f};
    for (int oc=0;oc<64;oc++){
        const float v = tp[(size_t)oc*HW];
#pragma unroll
        for (int k=0;k<6;k++) acc[k] += w[k*64+oc]*v;
    }
    float* f = g_feat + (size_t)n*6*HW + p;
#pragma unroll
    for (int k=0;k<6;k++) f[(size_t)k*HW] = acc[k];
}

// ---------------- K6: bilinear 32x32 -> 1024x1024 (half-pixel, clamped) ----
__global__ __launch_bounds__(256) void k_upsample(float* __restrict__ out)
{
    const int idx = blockIdx.x*256 + threadIdx.x;       // float4 units
    const int ox4 = idx & 255;
    const int oy  = (idx >> 8) & 1023;
    const int nk  = idx >> 18;
    if (nk >= NB*6) return;
    const float* f = g_feat + (size_t)nk*HW;

    const float sy = (oy + 0.5f)*0.03125f - 0.5f;
    const float fy = floorf(sy);
    const float wy = sy - fy;
    const int   iy = (int)fy;
    const int   y0 = min(max(iy,0),31);
    const int   y1 = min(iy+1,31);

    const int   ox0 = ox4*4;
    const float sx  = (ox0 + 0.5f)*0.03125f - 0.5f;
    const float fx  = floorf(sx);
    const float wx0 = sx - fx;
    const int   ix  = (int)fx;
    const int   x0  = min(max(ix,0),31);
    const int   x1  = min(ix+1,31);

    const float v00 = f[y0*32+x0], v01 = f[y0*32+x1];
    const float v10 = f[y1*32+x0], v11 = f[y1*32+x1];
    const float a = v00 + (v10-v00)*wy;
    const float b = v01 + (v11-v01)*wy;
    const float d = b - a;
    float4 o;
    o.x = a + d*wx0;
    o.y = a + d*(wx0+0.03125f);
    o.z = a + d*(wx0+0.0625f);
    o.w = a + d*(wx0+0.09375f);
    __stcs(&reinterpret_cast<float4*>(out)[idx], o);   // evict-first: write-once stream
}

// ---------------- launch ----------------------------------------------------
extern "C" void kernel_launch(void* const* d_in, const int* in_sizes, int n_in,
                              void* d_out, int out_size)
{
    (void)out_size;
    const float *x=0,*W1=0,*b1=0,*W3=0,*b3=0,*W5=0,*b5=0,*W7=0,*b7=0;
    const float *Wpe=0,*bpe=0,*lng=0,*lnb=0,*Wlast=0,*blast=0,*Wa0=0,*Was=0,*Wout=0;
    int c22=0, c64=0, c66=0;
    for (int i=0;i<n_in;i++){
        const int s = in_sizes[i];
        const float* p = (const float*)d_in[i];
        switch (s){
            case 7274496: x=p; break;
            case 56832:   W1=p; break;
            case 198:     W3=p; break;
            case 550:     W5=p; break;
            case 1078:    W7=p; break;
            case 594:     Wpe=p; break;
            case 38016:   Wlast=p; break;
            case 576:     Wa0=p; break;
            case 1600:    Was=p; break;
            case 384:     Wout=p; break;
            case 64:      if (c64==0) b1=p; else blast=p; c64++; break;
            case 22:      if (c22==0) b3=p; else if (c22==1) b5=p; else b7=p; c22++; break;
            case 66:      if (c66==0) bpe=p; else if (c66==1) lng=p; else lnb=p; c66++; break;
            default: break; // h, w scalars
        }
    }

    k_gemm     <<<dim3(16,NB), 256>>>(x, W1, b1);
    k_branch_pe<<<dim3(EC,NB), 256>>>(W3,b3,W5,b5,W7,b7,Wpe,bpe);
    k_mainconv <<<dim3(16,NB), 256>>>(lng,lnb,Wlast,blast);
    k_aux      <<<dim3(DC,NB), 256>>>(Wa0,Was);
    k_pw       <<<32, 256>>>(Wout);
    k_upsample <<<(NB*6*1024*256)/256, 256>>>((float*)d_out);
}